// round 2
// baseline (speedup 1.0000x reference)
#include <cuda_runtime.h>
#include <cuda_fp16.h>
#include <stdint.h>

#define BATCH   8192
#define K_DIM   2048
#define O_DIM   2048

#define TM 128          // out-dim tile
#define TN 256          // batch-dim tile
#define KC 64           // fp16 K per chunk (128 bytes/row)
#define NCHUNK (K_DIM / KC)   // 32

// ---------------- scratch (hi/lo fp16 splits) ----------------
__device__ __align__(128) __half g_At_hi[(size_t)O_DIM * K_DIM];  // W^T hi  [o][k]
__device__ __align__(128) __half g_At_lo[(size_t)O_DIM * K_DIM];  // W^T lo
__device__ __align__(128) __half g_X_hi[(size_t)BATCH * K_DIM];   // X hi    [b][k]
__device__ __align__(128) __half g_X_lo[(size_t)BATCH * K_DIM];   // X lo

// ---------------- helpers ----------------
__device__ __forceinline__ uint32_t smem_u32(const void* p) {
    uint32_t a;
    asm("{ .reg .u64 t; cvta.to.shared.u64 t, %1; cvt.u32.u64 %0, t; }" : "=r"(a) : "l"(p));
    return a;
}

__device__ __forceinline__ void cp_async16(uint32_t dst, const void* src) {
    asm volatile("cp.async.cg.shared.global [%0], [%1], 16;" :: "r"(dst), "l"(src) : "memory");
}
__device__ __forceinline__ void cp_async_commit() {
    asm volatile("cp.async.commit_group;" ::: "memory");
}
__device__ __forceinline__ void cp_async_wait1() {
    asm volatile("cp.async.wait_group 1;" ::: "memory");
}

__device__ __forceinline__ void ldsm_x4(uint32_t* r, uint32_t addr) {
    asm volatile("ldmatrix.sync.aligned.m8n8.x4.shared.b16 {%0,%1,%2,%3}, [%4];"
                 : "=r"(r[0]), "=r"(r[1]), "=r"(r[2]), "=r"(r[3]) : "r"(addr));
}

__device__ __forceinline__ void mma16816(float* c, const uint32_t* a, const uint32_t* b) {
    asm volatile(
        "mma.sync.aligned.m16n8k16.row.col.f32.f16.f16.f32 "
        "{%0,%1,%2,%3}, {%4,%5,%6,%7}, {%8,%9}, {%0,%1,%2,%3};"
        : "+f"(c[0]), "+f"(c[1]), "+f"(c[2]), "+f"(c[3])
        : "r"(a[0]), "r"(a[1]), "r"(a[2]), "r"(a[3]), "r"(b[0]), "r"(b[1]));
}

__device__ __forceinline__ uint32_t sw128(uint32_t off) {
    return off ^ ((off >> 3) & 0x70);
}

// ---------------- SMEM layout ----------------
// per stage: Ah 16KB | Al 16KB | Bh 32KB | Bl 32KB = 96KB. 2 stages.
#define ST_AH 0
#define ST_AL 16384
#define ST_BH 32768
#define ST_BL 65536
#define STAGE_BYTES 98304
#define SMEM_TOTAL (2 * STAGE_BYTES)   // 196608

// ---------------- conversion kernels ----------------
__global__ void convert_x_kernel(const float* __restrict__ x) {
    size_t n4 = (size_t)BATCH * K_DIM / 4;
    size_t stride = (size_t)gridDim.x * blockDim.x;
    for (size_t i = (size_t)blockIdx.x * blockDim.x + threadIdx.x; i < n4; i += stride) {
        float4 v = reinterpret_cast<const float4*>(x)[i];
        __half h0 = __float2half(v.x), h1 = __float2half(v.y);
        __half h2 = __float2half(v.z), h3 = __float2half(v.w);
        __half l0 = __float2half(v.x - __half2float(h0));
        __half l1 = __float2half(v.y - __half2float(h1));
        __half l2 = __float2half(v.z - __half2float(h2));
        __half l3 = __float2half(v.w - __half2float(h3));
        __half2* H = reinterpret_cast<__half2*>(g_X_hi);
        __half2* L = reinterpret_cast<__half2*>(g_X_lo);
        __half2 a, b;
        a.x = h0; a.y = h1; b.x = h2; b.y = h3;
        H[2 * i] = a; H[2 * i + 1] = b;
        a.x = l0; a.y = l1; b.x = l2; b.y = l3;
        L[2 * i] = a; L[2 * i + 1] = b;
    }
}

// Transpose W [k][o] -> At [o][k] with hi/lo split
__global__ void convert_w_kernel(const float* __restrict__ w) {
    __shared__ float tile[32][33];
    int o0 = blockIdx.x * 32;
    int k0 = blockIdx.y * 32;
    int tx = threadIdx.x, ty = threadIdx.y;
    tile[ty][tx] = w[(size_t)(k0 + ty) * O_DIM + o0 + tx];
    __syncthreads();
    float f = tile[tx][ty];  // = w[k0+tx][o0+ty]
    __half h = __float2half(f);
    __half l = __float2half(f - __half2float(h));
    size_t idx = (size_t)(o0 + ty) * K_DIM + (k0 + tx);
    g_At_hi[idx] = h;
    g_At_lo[idx] = l;
}

// ---------------- GEMM ----------------
__device__ __forceinline__ void issue_stage(uint32_t sbase, int o0, int b0, int chunk, int tid) {
    uint32_t st = sbase + (uint32_t)(chunk & 1) * STAGE_BYTES;
    int k0 = chunk * KC;
    // A mats: tid<128 -> Ah row tid ; tid>=128 -> Al row tid-128. 8 x 16B per row.
    {
        int row = tid & 127;
        const __half* src = (tid < 128) ? g_At_hi : g_At_lo;
        uint32_t dstb = st + ((tid < 128) ? ST_AH : ST_AL);
        const char* g = (const char*)(src + (size_t)(o0 + row) * K_DIM + k0);
        uint32_t rb = (uint32_t)row * 128;
#pragma unroll
        for (int c = 0; c < 8; c++)
            cp_async16(dstb + sw128(rb + c * 16), g + c * 16);
    }
    // B mats: every thread owns row tid for both Bh and Bl
    {
        const char* gh = (const char*)(g_X_hi + (size_t)(b0 + tid) * K_DIM + k0);
        const char* gl = (const char*)(g_X_lo + (size_t)(b0 + tid) * K_DIM + k0);
        uint32_t rb = (uint32_t)tid * 128;
#pragma unroll
        for (int c = 0; c < 8; c++)
            cp_async16(st + ST_BH + sw128(rb + c * 16), gh + c * 16);
#pragma unroll
        for (int c = 0; c < 8; c++)
            cp_async16(st + ST_BL + sw128(rb + c * 16), gl + c * 16);
    }
}

__global__ __launch_bounds__(256, 1)
void gemm_kernel(float* __restrict__ out) {
    extern __shared__ char smem[];
    uint32_t sbase = smem_u32(smem);
    int tid = threadIdx.x;
    int wid = tid >> 5, lane = tid & 31;
    int o0 = blockIdx.x * TM;
    int b0 = blockIdx.y * TN;
    int wm = (wid >> 2) * 64;   // warp M offset (2 rows of warps)
    int wn = (wid & 3) * 64;    // warp N offset (4 cols of warps)

    float c[4][8][4];
#pragma unroll
    for (int i = 0; i < 4; i++)
#pragma unroll
        for (int j = 0; j < 8; j++)
#pragma unroll
            for (int q = 0; q < 4; q++) c[i][j][q] = 0.0f;

    issue_stage(sbase, o0, b0, 0, tid); cp_async_commit();
    issue_stage(sbase, o0, b0, 1, tid); cp_async_commit();

    // precomputed ldmatrix row/col pieces
    int a_row = lane & 15;              // + wm + mt*16
    int a_cb  = (lane >> 4) << 4;       // byte offset within k16 group
    int b_row = ((lane >> 4) << 3) + (lane & 7);  // + wn + nt*16
    int b_cb  = ((lane >> 3) & 1) << 4;

    for (int i = 0; i < NCHUNK; i++) {
        cp_async_wait1();
        __syncthreads();
        uint32_t st = sbase + (uint32_t)(i & 1) * STAGE_BYTES;

#pragma unroll
        for (int kk = 0; kk < 4; kk++) {
            uint32_t ah[4][4], al[4][4], bh[8][2], bl[8][2];
#pragma unroll
            for (int mt = 0; mt < 4; mt++) {
                uint32_t off = (uint32_t)(wm + mt * 16 + a_row) * 128 + kk * 32 + a_cb;
                ldsm_x4(ah[mt], st + ST_AH + sw128(off));
                ldsm_x4(al[mt], st + ST_AL + sw128(off));
            }
#pragma unroll
            for (int nt = 0; nt < 4; nt++) {
                uint32_t off = (uint32_t)(wn + nt * 16 + b_row) * 128 + kk * 32 + b_cb;
                uint32_t r[4];
                ldsm_x4(r, st + ST_BH + sw128(off));
                bh[2 * nt][0] = r[0]; bh[2 * nt][1] = r[1];
                bh[2 * nt + 1][0] = r[2]; bh[2 * nt + 1][1] = r[3];
                ldsm_x4(r, st + ST_BL + sw128(off));
                bl[2 * nt][0] = r[0]; bl[2 * nt][1] = r[1];
                bl[2 * nt + 1][0] = r[2]; bl[2 * nt + 1][1] = r[3];
            }
#pragma unroll
            for (int mt = 0; mt < 4; mt++)
#pragma unroll
                for (int nt = 0; nt < 8; nt++)
                    mma16816(c[mt][nt], ah[mt], bh[nt]);
#pragma unroll
            for (int mt = 0; mt < 4; mt++)
#pragma unroll
                for (int nt = 0; nt < 8; nt++)
                    mma16816(c[mt][nt], ah[mt], bl[nt]);
#pragma unroll
            for (int mt = 0; mt < 4; mt++)
#pragma unroll
                for (int nt = 0; nt < 8; nt++)
                    mma16816(c[mt][nt], al[mt], bh[nt]);
        }

        __syncthreads();
        if (i + 2 < NCHUNK) issue_stage(sbase, o0, b0, i + 2, tid);
        cp_async_commit();   // keep group count uniform even when empty
    }

    // epilogue: direct stores, float2 per (frag, row-half)
    int r0 = o0 + wm + (lane >> 2);
    int col0 = b0 + wn + (lane & 3) * 2;
#pragma unroll
    for (int mt = 0; mt < 4; mt++) {
#pragma unroll
        for (int nt = 0; nt < 8; nt++) {
            int row = r0 + mt * 16;
            int col = col0 + nt * 8;
            float2 v0; v0.x = c[mt][nt][0]; v0.y = c[mt][nt][1];
            float2 v1; v1.x = c[mt][nt][2]; v1.y = c[mt][nt][3];
            *reinterpret_cast<float2*>(out + (size_t)row * BATCH + col) = v0;
            *reinterpret_cast<float2*>(out + (size_t)(row + 8) * BATCH + col) = v1;
        }
    }
}

// ---------------- launch ----------------
extern "C" void kernel_launch(void* const* d_in, const int* in_sizes, int n_in,
                              void* d_out, int out_size) {
    const float* in_values = (const float*)d_in[0];   // [8192, 2048]
    const float* weights   = (const float*)d_in[1];   // [2048, 2048]
    // d_in[2] = bias: intentionally unused (reference discards the add)
    float* out = (float*)d_out;                        // [2048, 8192]

    cudaFuncSetAttribute(gemm_kernel, cudaFuncAttributeMaxDynamicSharedMemorySize, SMEM_TOTAL);

    convert_x_kernel<<<4096, 256>>>(in_values);
    convert_w_kernel<<<dim3(O_DIM / 32, K_DIM / 32), dim3(32, 32)>>>(weights);
    gemm_kernel<<<dim3(O_DIM / TM, BATCH / TN), 256, SMEM_TOTAL>>>(out);
}

// round 3
// speedup vs baseline: 1.0068x; 1.0068x over previous
#include <cuda_runtime.h>
#include <cuda_fp16.h>
#include <stdint.h>

#define BATCH   8192
#define K_DIM   2048
#define O_DIM   2048

#define TM 128
#define TN 128
#define KC 64
#define NCHUNK (K_DIM / KC)   // 32

// ---------------- scratch (hi/lo fp16 splits) ----------------
__device__ __align__(128) __half g_At_hi[(size_t)O_DIM * K_DIM];  // W^T hi  [o][k]
__device__ __align__(128) __half g_At_lo[(size_t)O_DIM * K_DIM];  // W^T lo
__device__ __align__(128) __half g_X_hi[(size_t)BATCH * K_DIM];   // X hi    [b][k]
__device__ __align__(128) __half g_X_lo[(size_t)BATCH * K_DIM];   // X lo

// ---------------- helpers ----------------
__device__ __forceinline__ uint32_t smem_u32(const void* p) {
    uint32_t a;
    asm("{ .reg .u64 t; cvta.to.shared.u64 t, %1; cvt.u32.u64 %0, t; }" : "=r"(a) : "l"(p));
    return a;
}
__device__ __forceinline__ void cp_async16(uint32_t dst, const void* src) {
    asm volatile("cp.async.cg.shared.global [%0], [%1], 16;" :: "r"(dst), "l"(src) : "memory");
}
__device__ __forceinline__ void cp_async_commit() {
    asm volatile("cp.async.commit_group;" ::: "memory");
}
__device__ __forceinline__ void cp_async_wait1() {
    asm volatile("cp.async.wait_group 1;" ::: "memory");
}
__device__ __forceinline__ void ldsm_x4(uint32_t* r, uint32_t addr) {
    asm volatile("ldmatrix.sync.aligned.m8n8.x4.shared.b16 {%0,%1,%2,%3}, [%4];"
                 : "=r"(r[0]), "=r"(r[1]), "=r"(r[2]), "=r"(r[3]) : "r"(addr));
}
// fp32-accumulate HMMA
__device__ __forceinline__ void mma_f32(float* c, const uint32_t* a, const uint32_t* b) {
    asm volatile(
        "mma.sync.aligned.m16n8k16.row.col.f32.f16.f16.f32 "
        "{%0,%1,%2,%3}, {%4,%5,%6,%7}, {%8,%9}, {%0,%1,%2,%3};"
        : "+f"(c[0]), "+f"(c[1]), "+f"(c[2]), "+f"(c[3])
        : "r"(a[0]), "r"(a[1]), "r"(a[2]), "r"(a[3]), "r"(b[0]), "r"(b[1]));
}
// fp16-accumulate HMMA (correction terms)
__device__ __forceinline__ void mma_f16(uint32_t* c, const uint32_t* a, const uint32_t* b) {
    asm volatile(
        "mma.sync.aligned.m16n8k16.row.col.f16.f16.f16.f16 "
        "{%0,%1}, {%2,%3,%4,%5}, {%6,%7}, {%0,%1};"
        : "+r"(c[0]), "+r"(c[1])
        : "r"(a[0]), "r"(a[1]), "r"(a[2]), "r"(a[3]), "r"(b[0]), "r"(b[1]));
}
__device__ __forceinline__ uint32_t sw128(uint32_t off) {
    return off ^ ((off >> 3) & 0x70);
}

// ---------------- SMEM layout: 3 stages x 64KB ----------------
#define ST_AH 0
#define ST_AL 16384
#define ST_BH 32768
#define ST_BL 49152
#define STAGE_BYTES 65536
#define SMEM_TOTAL (3 * STAGE_BYTES)   // 196608

// ---------------- merged conversion kernel ----------------
// blocks [0, 4096): split X; blocks [4096, 8192): transpose+split W
__global__ __launch_bounds__(256)
void convert_kernel(const float* __restrict__ x, const float* __restrict__ w) {
    int tid = threadIdx.x;
    if (blockIdx.x < 4096) {
        // X: 8192*2048 floats = 4M float4; 1024 float4 per block
        size_t base = (size_t)blockIdx.x * 1024 + tid;
#pragma unroll
        for (int it = 0; it < 4; it++) {
            size_t i = base + (size_t)it * 256;
            float4 v = reinterpret_cast<const float4*>(x)[i];
            __half h0 = __float2half(v.x), h1 = __float2half(v.y);
            __half h2 = __float2half(v.z), h3 = __float2half(v.w);
            __half l0 = __float2half(v.x - __half2float(h0));
            __half l1 = __float2half(v.y - __half2float(h1));
            __half l2 = __float2half(v.z - __half2float(h2));
            __half l3 = __float2half(v.w - __half2float(h3));
            __half2* H = reinterpret_cast<__half2*>(g_X_hi);
            __half2* L = reinterpret_cast<__half2*>(g_X_lo);
            __half2 a, b;
            a.x = h0; a.y = h1; b.x = h2; b.y = h3;
            H[2 * i] = a; H[2 * i + 1] = b;
            a.x = l0; a.y = l1; b.x = l2; b.y = l3;
            L[2 * i] = a; L[2 * i + 1] = b;
        }
    } else {
        __shared__ float tile[32][33];
        int b = blockIdx.x - 4096;
        int o0 = (b & 63) * 32;
        int k0 = (b >> 6) * 32;
        int c = tid & 31, r8 = tid >> 5;
#pragma unroll
        for (int j = 0; j < 4; j++) {
            int r = r8 + 8 * j;
            tile[r][c] = w[(size_t)(k0 + r) * O_DIM + o0 + c];
        }
        __syncthreads();
#pragma unroll
        for (int j = 0; j < 4; j++) {
            int a = r8 + 8 * j;     // o offset
            float f = tile[c][a];   // w[k0+c][o0+a]
            __half h = __float2half(f);
            __half l = __float2half(f - __half2float(h));
            size_t idx = (size_t)(o0 + a) * K_DIM + (k0 + c);
            g_At_hi[idx] = h;
            g_At_lo[idx] = l;
        }
    }
}

// ---------------- GEMM ----------------
__device__ __forceinline__ void issue_stage(uint32_t sbase, int o0, int b0, int chunk, int tid) {
    uint32_t st = sbase + (uint32_t)(chunk % 3) * STAGE_BYTES;
    int k0 = chunk * KC;
    int row = tid & 127;
    bool hi = tid < 128;
    // A: 128 rows x 128B, hi half of threads -> Ah, lo half -> Al
    {
        const __half* src = hi ? g_At_hi : g_At_lo;
        uint32_t dstb = st + (hi ? ST_AH : ST_AL);
        const char* g = (const char*)(src + (size_t)(o0 + row) * K_DIM + k0);
        uint32_t rb = (uint32_t)row * 128;
#pragma unroll
        for (int c = 0; c < 8; c++)
            cp_async16(dstb + sw128(rb + c * 16), g + c * 16);
    }
    // B: 128 rows x 128B
    {
        const __half* src = hi ? g_X_hi : g_X_lo;
        uint32_t dstb = st + (hi ? ST_BH : ST_BL);
        const char* g = (const char*)(src + (size_t)(b0 + row) * K_DIM + k0);
        uint32_t rb = (uint32_t)row * 128;
#pragma unroll
        for (int c = 0; c < 8; c++)
            cp_async16(dstb + sw128(rb + c * 16), g + c * 16);
    }
}

__global__ __launch_bounds__(256, 1)
void gemm_kernel(float* __restrict__ out) {
    extern __shared__ char smem[];
    uint32_t sbase = smem_u32(smem);
    int tid = threadIdx.x;
    int wid = tid >> 5, lane = tid & 31;
    int o0 = blockIdx.x * TM;
    int b0 = blockIdx.y * TN;
    int wm = (wid >> 2) * 64;   // 2 warp rows
    int wn = (wid & 3) * 32;    // 4 warp cols

    float    c[4][4][4];    // hi*hi, fp32 acc
    uint32_t cc[4][4][2];   // hi*lo + lo*hi, fp16 acc (packed f16x2)
#pragma unroll
    for (int i = 0; i < 4; i++)
#pragma unroll
        for (int j = 0; j < 4; j++) {
#pragma unroll
            for (int q = 0; q < 4; q++) c[i][j][q] = 0.0f;
            cc[i][j][0] = 0u; cc[i][j][1] = 0u;
        }

    issue_stage(sbase, o0, b0, 0, tid); cp_async_commit();
    issue_stage(sbase, o0, b0, 1, tid); cp_async_commit();

    int a_row = lane & 15;
    int a_cb  = (lane >> 4) << 4;
    int b_row = ((lane >> 4) << 3) + (lane & 7);
    int b_cb  = ((lane >> 3) & 1) << 4;

    for (int i = 0; i < NCHUNK; i++) {
        cp_async_wait1();
        __syncthreads();
        if (i + 2 < NCHUNK) issue_stage(sbase, o0, b0, i + 2, tid);
        cp_async_commit();

        uint32_t st = sbase + (uint32_t)(i % 3) * STAGE_BYTES;
#pragma unroll
        for (int kk = 0; kk < 4; kk++) {
            uint32_t ah[4][4], al[4][4];
#pragma unroll
            for (int mt = 0; mt < 4; mt++) {
                uint32_t off = (uint32_t)(wm + mt * 16 + a_row) * 128 + kk * 32 + a_cb;
                uint32_t sw = sw128(off);
                ldsm_x4(ah[mt], st + ST_AH + sw);
                ldsm_x4(al[mt], st + ST_AL + sw);
            }
#pragma unroll
            for (int nt = 0; nt < 2; nt++) {
                uint32_t off = (uint32_t)(wn + nt * 16 + b_row) * 128 + kk * 32 + b_cb;
                uint32_t sw = sw128(off);
                uint32_t bh[4];
                ldsm_x4(bh, st + ST_BH + sw);
#pragma unroll
                for (int mt = 0; mt < 4; mt++) {
                    mma_f32(c[mt][2 * nt],     ah[mt], bh);
                    mma_f32(c[mt][2 * nt + 1], ah[mt], bh + 2);
                }
#pragma unroll
                for (int mt = 0; mt < 4; mt++) {
                    mma_f16(cc[mt][2 * nt],     al[mt], bh);
                    mma_f16(cc[mt][2 * nt + 1], al[mt], bh + 2);
                }
                uint32_t bl[4];
                ldsm_x4(bl, st + ST_BL + sw);
#pragma unroll
                for (int mt = 0; mt < 4; mt++) {
                    mma_f16(cc[mt][2 * nt],     ah[mt], bl);
                    mma_f16(cc[mt][2 * nt + 1], ah[mt], bl + 2);
                }
            }
        }
        __syncthreads();
    }

    // epilogue: out = c_f32 + float(c_f16corr)
    int r0 = o0 + wm + (lane >> 2);
    int col0 = b0 + wn + (lane & 3) * 2;
#pragma unroll
    for (int mt = 0; mt < 4; mt++) {
#pragma unroll
        for (int nt = 0; nt < 4; nt++) {
            int row = r0 + mt * 16;
            int col = col0 + nt * 8;
            float2 k0 = __half22float2(*reinterpret_cast<__half2*>(&cc[mt][nt][0]));
            float2 k1 = __half22float2(*reinterpret_cast<__half2*>(&cc[mt][nt][1]));
            float2 v0, v1;
            v0.x = c[mt][nt][0] + k0.x; v0.y = c[mt][nt][1] + k0.y;
            v1.x = c[mt][nt][2] + k1.x; v1.y = c[mt][nt][3] + k1.y;
            *reinterpret_cast<float2*>(out + (size_t)row * BATCH + col) = v0;
            *reinterpret_cast<float2*>(out + (size_t)(row + 8) * BATCH + col) = v1;
        }
    }
}

// ---------------- launch ----------------
extern "C" void kernel_launch(void* const* d_in, const int* in_sizes, int n_in,
                              void* d_out, int out_size) {
    const float* in_values = (const float*)d_in[0];   // [8192, 2048]
    const float* weights   = (const float*)d_in[1];   // [2048, 2048]
    // d_in[2] = bias: intentionally unused (reference discards the add)
    float* out = (float*)d_out;                        // [2048, 8192]

    cudaFuncSetAttribute(gemm_kernel, cudaFuncAttributeMaxDynamicSharedMemorySize, SMEM_TOTAL);

    convert_kernel<<<8192, 256>>>(in_values, weights);
    gemm_kernel<<<dim3(O_DIM / TM, BATCH / TN), 256, SMEM_TOTAL>>>(out);
}

// round 4
// speedup vs baseline: 1.0080x; 1.0012x over previous
#include <cuda_runtime.h>
#include <cuda_fp16.h>
#include <stdint.h>

#define BATCH   8192
#define K_DIM   2048
#define O_DIM   2048

#define TM 128
#define TN 128
#define KC 64
#define NCHUNK (K_DIM / KC)   // 32

// ---------------- scratch (hi/lo fp16 splits) ----------------
__device__ __align__(128) __half g_At_hi[(size_t)O_DIM * K_DIM];  // W^T hi  [o][k]
__device__ __align__(128) __half g_At_lo[(size_t)O_DIM * K_DIM];  // W^T lo
__device__ __align__(128) __half g_X_hi[(size_t)BATCH * K_DIM];   // X hi    [b][k]
__device__ __align__(128) __half g_X_lo[(size_t)BATCH * K_DIM];   // X lo

// ---------------- helpers ----------------
__device__ __forceinline__ uint32_t smem_u32(const void* p) {
    uint32_t a;
    asm("{ .reg .u64 t; cvta.to.shared.u64 t, %1; cvt.u32.u64 %0, t; }" : "=r"(a) : "l"(p));
    return a;
}
__device__ __forceinline__ void cp_async16(uint32_t dst, const void* src) {
    asm volatile("cp.async.cg.shared.global [%0], [%1], 16;" :: "r"(dst), "l"(src) : "memory");
}
__device__ __forceinline__ void cp_async_commit() {
    asm volatile("cp.async.commit_group;" ::: "memory");
}
__device__ __forceinline__ void cp_async_wait1() {
    asm volatile("cp.async.wait_group 1;" ::: "memory");
}
__device__ __forceinline__ void ldsm_x4(uint32_t* r, uint32_t addr) {
    asm volatile("ldmatrix.sync.aligned.m8n8.x4.shared.b16 {%0,%1,%2,%3}, [%4];"
                 : "=r"(r[0]), "=r"(r[1]), "=r"(r[2]), "=r"(r[3]) : "r"(addr));
}
// fp32-accumulate HMMA
__device__ __forceinline__ void mma_f32(float* c, const uint32_t* a, const uint32_t* b) {
    asm volatile(
        "mma.sync.aligned.m16n8k16.row.col.f32.f16.f16.f32 "
        "{%0,%1,%2,%3}, {%4,%5,%6,%7}, {%8,%9}, {%0,%1,%2,%3};"
        : "+f"(c[0]), "+f"(c[1]), "+f"(c[2]), "+f"(c[3])
        : "r"(a[0]), "r"(a[1]), "r"(a[2]), "r"(a[3]), "r"(b[0]), "r"(b[1]));
}
// fp16-accumulate HMMA (correction terms)
__device__ __forceinline__ void mma_f16(uint32_t* c, const uint32_t* a, const uint32_t* b) {
    asm volatile(
        "mma.sync.aligned.m16n8k16.row.col.f16.f16.f16.f16 "
        "{%0,%1}, {%2,%3,%4,%5}, {%6,%7}, {%0,%1};"
        : "+r"(c[0]), "+r"(c[1])
        : "r"(a[0]), "r"(a[1]), "r"(a[2]), "r"(a[3]), "r"(b[0]), "r"(b[1]));
}
__device__ __forceinline__ uint32_t sw128(uint32_t off) {
    return off ^ ((off >> 3) & 0x70);
}

// ---------------- SMEM layout: 3 stages x 64KB ----------------
#define ST_AH 0
#define ST_AL 16384
#define ST_BH 32768
#define ST_BL 49152
#define STAGE_BYTES 65536
#define SMEM_TOTAL (3 * STAGE_BYTES)   // 196608

// ---------------- merged conversion kernel ----------------
__global__ __launch_bounds__(256)
void convert_kernel(const float* __restrict__ x, const float* __restrict__ w) {
    int tid = threadIdx.x;
    if (blockIdx.x < 4096) {
        size_t base = (size_t)blockIdx.x * 1024 + tid;
#pragma unroll
        for (int it = 0; it < 4; it++) {
            size_t i = base + (size_t)it * 256;
            float4 v = reinterpret_cast<const float4*>(x)[i];
            __half h0 = __float2half(v.x), h1 = __float2half(v.y);
            __half h2 = __float2half(v.z), h3 = __float2half(v.w);
            __half l0 = __float2half(v.x - __half2float(h0));
            __half l1 = __float2half(v.y - __half2float(h1));
            __half l2 = __float2half(v.z - __half2float(h2));
            __half l3 = __float2half(v.w - __half2float(h3));
            __half2* H = reinterpret_cast<__half2*>(g_X_hi);
            __half2* L = reinterpret_cast<__half2*>(g_X_lo);
            __half2 a, b;
            a.x = h0; a.y = h1; b.x = h2; b.y = h3;
            H[2 * i] = a; H[2 * i + 1] = b;
            a.x = l0; a.y = l1; b.x = l2; b.y = l3;
            L[2 * i] = a; L[2 * i + 1] = b;
        }
    } else {
        __shared__ float tile[32][33];
        int b = blockIdx.x - 4096;
        int o0 = (b & 63) * 32;
        int k0 = (b >> 6) * 32;
        int c = tid & 31, r8 = tid >> 5;
#pragma unroll
        for (int j = 0; j < 4; j++) {
            int r = r8 + 8 * j;
            tile[r][c] = w[(size_t)(k0 + r) * O_DIM + o0 + c];
        }
        __syncthreads();
#pragma unroll
        for (int j = 0; j < 4; j++) {
            int a = r8 + 8 * j;     // o offset
            float f = tile[c][a];   // w[k0+c][o0+a]
            __half h = __float2half(f);
            __half l = __float2half(f - __half2float(h));
            size_t idx = (size_t)(o0 + a) * K_DIM + (k0 + c);
            g_At_hi[idx] = h;
            g_At_lo[idx] = l;
        }
    }
}

// ---------------- GEMM ----------------
// 512 threads: quarter q = tid>>7 selects {Ah, Al, Bh, Bl}, row = tid&127, 8x16B per row.
__device__ __forceinline__ void issue_stage(uint32_t sbase, int o0, int b0, int chunk, int tid) {
    uint32_t st = sbase + (uint32_t)(chunk % 3) * STAGE_BYTES;
    int k0 = chunk * KC;
    int q = tid >> 7;
    int row = tid & 127;
    const __half* src = (q == 0) ? g_At_hi : (q == 1) ? g_At_lo : (q == 2) ? g_X_hi : g_X_lo;
    int gr = (q < 2) ? o0 + row : b0 + row;
    uint32_t dstb = st + (uint32_t)q * 16384;
    const char* g = (const char*)(src + (size_t)gr * K_DIM + k0);
    uint32_t rb = (uint32_t)row * 128;
#pragma unroll
    for (int c = 0; c < 8; c++)
        cp_async16(dstb + sw128(rb + c * 16), g + c * 16);
}

__global__ __launch_bounds__(512, 1)
void gemm_kernel(float* __restrict__ out) {
    extern __shared__ char smem[];
    uint32_t sbase = smem_u32(smem);
    int tid = threadIdx.x;
    int wid = tid >> 5, lane = tid & 31;
    int o0 = blockIdx.x * TM;
    int b0 = blockIdx.y * TN;
    int wm = (wid >> 2) * 32;   // 4 warp rows
    int wn = (wid & 3) * 32;    // 4 warp cols

    float    c[2][4][4];    // hi*hi, fp32 acc
    uint32_t cc[2][4][2];   // hi*lo + lo*hi, fp16 acc (packed f16x2)
#pragma unroll
    for (int i = 0; i < 2; i++)
#pragma unroll
        for (int j = 0; j < 4; j++) {
#pragma unroll
            for (int q = 0; q < 4; q++) c[i][j][q] = 0.0f;
            cc[i][j][0] = 0u; cc[i][j][1] = 0u;
        }

    issue_stage(sbase, o0, b0, 0, tid); cp_async_commit();
    issue_stage(sbase, o0, b0, 1, tid); cp_async_commit();

    int a_row = lane & 15;
    int a_cb  = (lane >> 4) << 4;
    int b_row = ((lane >> 4) << 3) + (lane & 7);
    int b_cb  = ((lane >> 3) & 1) << 4;

    for (int i = 0; i < NCHUNK; i++) {
        cp_async_wait1();
        __syncthreads();
        if (i + 2 < NCHUNK) issue_stage(sbase, o0, b0, i + 2, tid);
        cp_async_commit();

        uint32_t st = sbase + (uint32_t)(i % 3) * STAGE_BYTES;
#pragma unroll
        for (int kk = 0; kk < 4; kk++) {
            uint32_t ah[2][4], al[2][4];
#pragma unroll
            for (int mt = 0; mt < 2; mt++) {
                uint32_t off = (uint32_t)(wm + mt * 16 + a_row) * 128 + kk * 32 + a_cb;
                uint32_t sw = sw128(off);
                ldsm_x4(ah[mt], st + ST_AH + sw);
                ldsm_x4(al[mt], st + ST_AL + sw);
            }
#pragma unroll
            for (int nt = 0; nt < 2; nt++) {
                uint32_t off = (uint32_t)(wn + nt * 16 + b_row) * 128 + kk * 32 + b_cb;
                uint32_t sw = sw128(off);
                uint32_t bh[4];
                ldsm_x4(bh, st + ST_BH + sw);
#pragma unroll
                for (int mt = 0; mt < 2; mt++) {
                    mma_f32(c[mt][2 * nt],     ah[mt], bh);
                    mma_f32(c[mt][2 * nt + 1], ah[mt], bh + 2);
                }
#pragma unroll
                for (int mt = 0; mt < 2; mt++) {
                    mma_f16(cc[mt][2 * nt],     al[mt], bh);
                    mma_f16(cc[mt][2 * nt + 1], al[mt], bh + 2);
                }
                uint32_t bl[4];
                ldsm_x4(bl, st + ST_BL + sw);
#pragma unroll
                for (int mt = 0; mt < 2; mt++) {
                    mma_f16(cc[mt][2 * nt],     ah[mt], bl);
                    mma_f16(cc[mt][2 * nt + 1], ah[mt], bl + 2);
                }
            }
        }
        __syncthreads();
    }

    // epilogue: out = c_f32 + float(c_f16corr)
    int r0 = o0 + wm + (lane >> 2);
    int col0 = b0 + wn + (lane & 3) * 2;
#pragma unroll
    for (int mt = 0; mt < 2; mt++) {
#pragma unroll
        for (int nt = 0; nt < 4; nt++) {
            int row = r0 + mt * 16;
            int col = col0 + nt * 8;
            float2 k0 = __half22float2(*reinterpret_cast<__half2*>(&cc[mt][nt][0]));
            float2 k1 = __half22float2(*reinterpret_cast<__half2*>(&cc[mt][nt][1]));
            float2 v0, v1;
            v0.x = c[mt][nt][0] + k0.x; v0.y = c[mt][nt][1] + k0.y;
            v1.x = c[mt][nt][2] + k1.x; v1.y = c[mt][nt][3] + k1.y;
            *reinterpret_cast<float2*>(out + (size_t)row * BATCH + col) = v0;
            *reinterpret_cast<float2*>(out + (size_t)(row + 8) * BATCH + col) = v1;
        }
    }
}

// ---------------- launch ----------------
extern "C" void kernel_launch(void* const* d_in, const int* in_sizes, int n_in,
                              void* d_out, int out_size) {
    const float* in_values = (const float*)d_in[0];   // [8192, 2048]
    const float* weights   = (const float*)d_in[1];   // [2048, 2048]
    // d_in[2] = bias: intentionally unused (reference discards the add)
    float* out = (float*)d_out;                        // [2048, 8192]

    cudaFuncSetAttribute(gemm_kernel, cudaFuncAttributeMaxDynamicSharedMemorySize, SMEM_TOTAL);

    convert_kernel<<<8192, 256>>>(in_values, weights);
    gemm_kernel<<<dim3(O_DIM / TM, BATCH / TN), 512, SMEM_TOTAL>>>(out);
}

// round 6
// speedup vs baseline: 2.3757x; 2.3569x over previous
#include <cuda_runtime.h>
#include <cuda_fp16.h>
#include <stdint.h>

#define BATCH   8192
#define K_DIM   2048
#define O_DIM   2048

#define TM 256
#define TN 128
#define KC 64
#define NCHUNK (K_DIM / KC)   // 32

// ---------------- scratch ----------------
__device__ __align__(128) __half g_At_hi[(size_t)O_DIM * K_DIM];  // W^T hi  [o][k]
__device__ __align__(128) __half g_X_hi[(size_t)BATCH * K_DIM];   // X hi    [b][k]
__device__ __align__(128) __half g_X_lo[(size_t)BATCH * K_DIM];   // X lo

// ---------------- helpers ----------------
__device__ __forceinline__ uint32_t smem_u32(const void* p) {
    uint32_t a;
    asm("{ .reg .u64 t; cvta.to.shared.u64 t, %1; cvt.u32.u64 %0, t; }" : "=r"(a) : "l"(p));
    return a;
}
__device__ __forceinline__ void cp_async16(uint32_t dst, const void* src) {
    asm volatile("cp.async.cg.shared.global [%0], [%1], 16;" :: "r"(dst), "l"(src) : "memory");
}
__device__ __forceinline__ void cp_async_commit() {
    asm volatile("cp.async.commit_group;" ::: "memory");
}
__device__ __forceinline__ void cp_async_wait1() {
    asm volatile("cp.async.wait_group 1;" ::: "memory");
}
__device__ __forceinline__ void ldsm_x4(uint32_t* r, uint32_t addr) {
    asm volatile("ldmatrix.sync.aligned.m8n8.x4.shared.b16 {%0,%1,%2,%3}, [%4];"
                 : "=r"(r[0]), "=r"(r[1]), "=r"(r[2]), "=r"(r[3]) : "r"(addr));
}
__device__ __forceinline__ void mma_f32(float* c, const uint32_t* a, const uint32_t* b) {
    asm volatile(
        "mma.sync.aligned.m16n8k16.row.col.f32.f16.f16.f32 "
        "{%0,%1,%2,%3}, {%4,%5,%6,%7}, {%8,%9}, {%0,%1,%2,%3};"
        : "+f"(c[0]), "+f"(c[1]), "+f"(c[2]), "+f"(c[3])
        : "r"(a[0]), "r"(a[1]), "r"(a[2]), "r"(a[3]), "r"(b[0]), "r"(b[1]));
}
__device__ __forceinline__ void mma_f16(uint32_t* c, const uint32_t* a, const uint32_t* b) {
    asm volatile(
        "mma.sync.aligned.m16n8k16.row.col.f16.f16.f16.f16 "
        "{%0,%1}, {%2,%3,%4,%5}, {%6,%7}, {%0,%1};"
        : "+r"(c[0]), "+r"(c[1])
        : "r"(a[0]), "r"(a[1]), "r"(a[2]), "r"(a[3]), "r"(b[0]), "r"(b[1]));
}
__device__ __forceinline__ uint32_t sw128(uint32_t off) {
    return off ^ ((off >> 3) & 0x70);
}

// ---------------- SMEM layout: 3 stages x 64KB ----------------
// per stage: Ah 32KB (256 rows x 128B) | Bh 16KB | Bl 16KB
#define ST_AH 0
#define ST_BH 32768
#define ST_BL 49152
#define STAGE_BYTES 65536
#define SMEM_TOTAL (3 * STAGE_BYTES)   // 196608

// ---------------- merged conversion kernel ----------------
// blocks [0,4096): split X into hi/lo; blocks [4096,8192): transpose W -> At hi only
__global__ __launch_bounds__(256)
void convert_kernel(const float* __restrict__ x, const float* __restrict__ w) {
    int tid = threadIdx.x;
    if (blockIdx.x < 4096) {
        size_t base = (size_t)blockIdx.x * 1024 + tid;
#pragma unroll
        for (int it = 0; it < 4; it++) {
            size_t i = base + (size_t)it * 256;
            float4 v = reinterpret_cast<const float4*>(x)[i];
            __half h0 = __float2half(v.x), h1 = __float2half(v.y);
            __half h2 = __float2half(v.z), h3 = __float2half(v.w);
            __half l0 = __float2half(v.x - __half2float(h0));
            __half l1 = __float2half(v.y - __half2float(h1));
            __half l2 = __float2half(v.z - __half2float(h2));
            __half l3 = __float2half(v.w - __half2float(h3));
            __half2* H = reinterpret_cast<__half2*>(g_X_hi);
            __half2* L = reinterpret_cast<__half2*>(g_X_lo);
            __half2 a, b;
            a.x = h0; a.y = h1; b.x = h2; b.y = h3;
            H[2 * i] = a; H[2 * i + 1] = b;
            a.x = l0; a.y = l1; b.x = l2; b.y = l3;
            L[2 * i] = a; L[2 * i + 1] = b;
        }
    } else {
        __shared__ float tile[32][33];
        int b = blockIdx.x - 4096;
        int o0 = (b & 63) * 32;
        int k0 = (b >> 6) * 32;
        int c = tid & 31, r8 = tid >> 5;
#pragma unroll
        for (int j = 0; j < 4; j++) {
            int r = r8 + 8 * j;
            tile[r][c] = w[(size_t)(k0 + r) * O_DIM + o0 + c];
        }
        __syncthreads();
#pragma unroll
        for (int j = 0; j < 4; j++) {
            int a = r8 + 8 * j;     // o offset
            float f = tile[c][a];   // w[k0+c][o0+a]
            g_At_hi[(size_t)(o0 + a) * K_DIM + (k0 + c)] = __float2half(f);
        }
    }
}

// ---------------- GEMM ----------------
// 256 threads. Stage = 512 logical rows of 128B:
//   rows [0,256)   = Ah
//   rows [256,384) = Bh
//   rows [384,512) = Bl
// iter it in [0,16): row = it*32 + tid/8, col = tid%8  (lanes cover full 128B rows
// -> 4 gmem lines per warp instruction, fully coalesced)
__device__ __forceinline__ void issue_stage(uint32_t sbase, int o0, int b0, int chunk, int tid) {
    uint32_t st = sbase + (uint32_t)(chunk % 3) * STAGE_BYTES;
    int k0 = chunk * KC;
    int rsub = tid >> 3;        // 0..31
    int col = tid & 7;          // 16B column
#pragma unroll
    for (int it = 0; it < 16; it++) {
        int row = it * 32 + rsub;
        const __half* src;
        uint32_t dstb;
        int grow, lrow;
        if (it < 8)       { src = g_At_hi; dstb = st + ST_AH; grow = o0 + row;        lrow = row; }
        else if (it < 12) { src = g_X_hi;  dstb = st + ST_BH; grow = b0 + row - 256;  lrow = row - 256; }
        else              { src = g_X_lo;  dstb = st + ST_BL; grow = b0 + row - 384;  lrow = row - 384; }
        const char* g = (const char*)(src + (size_t)grow * K_DIM + k0) + col * 16;
        cp_async16(dstb + sw128((uint32_t)lrow * 128 + col * 16), g);
    }
}

__global__ __launch_bounds__(256, 1)
void gemm_kernel(float* __restrict__ out) {
    extern __shared__ char smem[];
    uint32_t sbase = smem_u32(smem);
    int tid = threadIdx.x;
    int wid = tid >> 5, lane = tid & 31;
    int o0 = blockIdx.x * TM;
    int b0 = blockIdx.y * TN;
    int wm = (wid >> 1) * 64;   // 4 warp rows (M)
    int wn = (wid & 1) * 64;    // 2 warp cols (N)

    float    c[4][8][4];    // hi*hi, fp32 acc   (warp tile 64x64)
    uint32_t cc[4][8][2];   // Ah*Bl corr, f16 acc
#pragma unroll
    for (int i = 0; i < 4; i++)
#pragma unroll
        for (int j = 0; j < 8; j++) {
#pragma unroll
            for (int q = 0; q < 4; q++) c[i][j][q] = 0.0f;
            cc[i][j][0] = 0u; cc[i][j][1] = 0u;
        }

    issue_stage(sbase, o0, b0, 0, tid); cp_async_commit();
    issue_stage(sbase, o0, b0, 1, tid); cp_async_commit();

    int a_row = lane & 15;
    int a_cb  = (lane >> 4) << 4;
    int b_row = ((lane >> 4) << 3) + (lane & 7);
    int b_cb  = ((lane >> 3) & 1) << 4;

    for (int i = 0; i < NCHUNK; i++) {
        cp_async_wait1();
        __syncthreads();
        if (i + 2 < NCHUNK) issue_stage(sbase, o0, b0, i + 2, tid);
        cp_async_commit();

        uint32_t st = sbase + (uint32_t)(i % 3) * STAGE_BYTES;
#pragma unroll
        for (int kk = 0; kk < 4; kk++) {
            uint32_t ah[4][4];
#pragma unroll
            for (int mt = 0; mt < 4; mt++) {
                uint32_t off = (uint32_t)(wm + mt * 16 + a_row) * 128 + kk * 32 + a_cb;
                ldsm_x4(ah[mt], st + ST_AH + sw128(off));
            }
#pragma unroll
            for (int nt = 0; nt < 4; nt++) {
                uint32_t off = (uint32_t)(wn + nt * 16 + b_row) * 128 + kk * 32 + b_cb;
                uint32_t sw = sw128(off);
                uint32_t bh[4];
                ldsm_x4(bh, st + ST_BH + sw);
#pragma unroll
                for (int mt = 0; mt < 4; mt++) {
                    mma_f32(c[mt][2 * nt],     ah[mt], bh);
                    mma_f32(c[mt][2 * nt + 1], ah[mt], bh + 2);
                }
                uint32_t bl[4];
                ldsm_x4(bl, st + ST_BL + sw);
#pragma unroll
                for (int mt = 0; mt < 4; mt++) {
                    mma_f16(cc[mt][2 * nt],     ah[mt], bl);
                    mma_f16(cc[mt][2 * nt + 1], ah[mt], bl + 2);
                }
            }
        }
        __syncthreads();
    }

    // epilogue: out = c_f32 + float(c_f16corr)
    int r0 = o0 + wm + (lane >> 2);
    int col0 = b0 + wn + (lane & 3) * 2;
#pragma unroll
    for (int mt = 0; mt < 4; mt++) {
#pragma unroll
        for (int nt = 0; nt < 8; nt++) {
            int row = r0 + mt * 16;
            int col = col0 + nt * 8;
            float2 k0 = __half22float2(*reinterpret_cast<__half2*>(&cc[mt][nt][0]));
            float2 k1 = __half22float2(*reinterpret_cast<__half2*>(&cc[mt][nt][1]));
            float2 v0, v1;
            v0.x = c[mt][nt][0] + k0.x; v0.y = c[mt][nt][1] + k0.y;
            v1.x = c[mt][nt][2] + k1.x; v1.y = c[mt][nt][3] + k1.y;
            *reinterpret_cast<float2*>(out + (size_t)row * BATCH + col) = v0;
            *reinterpret_cast<float2*>(out + (size_t)(row + 8) * BATCH + col) = v1;
        }
    }
}

// ---------------- launch ----------------
extern "C" void kernel_launch(void* const* d_in, const int* in_sizes, int n_in,
                              void* d_out, int out_size) {
    const float* in_values = (const float*)d_in[0];   // [8192, 2048]
    const float* weights   = (const float*)d_in[1];   // [2048, 2048]
    // d_in[2] = bias: intentionally unused (reference discards the add)
    float* out = (float*)d_out;                        // [2048, 8192]

    cudaFuncSetAttribute(gemm_kernel, cudaFuncAttributeMaxDynamicSharedMemorySize, SMEM_TOTAL);

    convert_kernel<<<8192, 256>>>(in_values, weights);
    gemm_kernel<<<dim3(O_DIM / TM, BATCH / TN), 256, SMEM_TOTAL>>>(out);
}